// round 15
// baseline (speedup 1.0000x reference)
#include <cuda_runtime.h>

// Warper3d: 3D trilinear warp (grid_sample, align_corners=False, border pad).
//   img : [B=4, 1, D=64, H=192, W=192] f32
//   flow: [B=4, 3, D=64, H=192, W=192] f32
//   out : [B=4, 1, D=64, H=192, W=192] f32
//
// Model (R3-R11): L1tex sector-visit bound; invariant ~70us across MLP and
// lane mappings (L1 pinned 80-82%). This version cuts per-voxel gather
// sector-visits 8 -> ~6: each row's (x0,x1) pair is fetched with ONE aligned
// float2 at x0&~1 (covers both when x0 even, 50%) plus a predicated scalar
// fallback for x1 when x0 odd. 8B lanes keep the sector byte budget
// (R5's 16B float4 violated it and regressed). Base config = R6 (best).
// (R12-R14 benches were infra failures — resubmitting unchanged.)

#define BB 4
#define DD 64
#define HH 192
#define WW 192
#define SP (DD * HH * WW)

#define TX 48      // threads in x; each thread does 2 consecutive x voxels
#define TY 2
#define TZ 2

// (v[x0], v[x1]) from one aligned float2 + rare predicated scalar.
// x0 in [0,191]; base = x0&~1 in [0,190] -> float2 is 8B aligned, in-bounds.
__device__ __forceinline__ float2 gather_pair(const float* __restrict__ row,
                                              int x0, int x1, bool even)
{
    float2 f = __ldg((const float2*)(row + (x0 & ~1)));
    float v0 = even ? f.x : f.y;
    float v1 = even ? f.y : __ldg(row + x1);   // predicated; x0==191 -> x1==191
    return make_float2(v0, v1);
}

__global__ __launch_bounds__(TX * TY * TZ)
void warp3d_kernel(const float* __restrict__ img,
                   const float* __restrict__ flow,
                   float* __restrict__ out)
{
    int xp = (blockIdx.x * TX + threadIdx.x) * 2;      // even; covers xp, xp+1
    int y  = blockIdx.y * TY + threadIdx.y;
    int zb = blockIdx.z;                               // z-tile (32) x batch (4)
    int z  = (zb & 31) * TZ + threadIdx.z;
    int b  = zb >> 5;

    int s = (z * HH + y) * WW + xp;                    // even => 8B aligned

    const float* fb = flow + (size_t)b * 3 * SP;
    float2 fx = __ldcs((const float2*)(fb + s));
    float2 fy = __ldcs((const float2*)(fb + SP + s));
    float2 fz = __ldcs((const float2*)(fb + 2 * SP + s));

    // Reference composition gx=2v/(S-1)-1; ix=((gx+1)*S-1)/2 == v*S/(S-1)-0.5
    const float KX = (float)WW / (float)(WW - 1);
    const float KY = (float)HH / (float)(HH - 1);
    const float KZ = (float)DD / (float)(DD - 1);

    const float* ib = img + (size_t)b * SP;

    float res[2];
    const float fxa[2] = {fx.x, fx.y};
    const float fya[2] = {fy.x, fy.y};
    const float fza[2] = {fz.x, fz.y};

    #pragma unroll
    for (int k = 0; k < 2; k++) {
        float ix = fmaf((float)(xp + k) + fxa[k], KX, -0.5f);
        float iy = fmaf((float)y + fya[k],        KY, -0.5f);
        float iz = fmaf((float)z + fza[k],        KZ, -0.5f);
        ix = fminf(fmaxf(ix, 0.0f), (float)(WW - 1));
        iy = fminf(fmaxf(iy, 0.0f), (float)(HH - 1));
        iz = fminf(fmaxf(iz, 0.0f), (float)(DD - 1));

        float x0f = floorf(ix); float wx = ix - x0f;
        float y0f = floorf(iy); float wy = iy - y0f;
        float z0f = floorf(iz); float wz = iz - z0f;

        int x0 = (int)x0f; int x1 = min(x0 + 1, WW - 1);
        int y0 = (int)y0f; int y1 = min(y0 + 1, HH - 1);
        int z0 = (int)z0f; int z1 = min(z0 + 1, DD - 1);
        bool even = (x0 & 1) == 0;

        const float* p00 = ib + (z0 * HH + y0) * WW;
        const float* p01 = ib + (z0 * HH + y1) * WW;
        const float* p10 = ib + (z1 * HH + y0) * WW;
        const float* p11 = ib + (z1 * HH + y1) * WW;

        float2 g00 = gather_pair(p00, x0, x1, even);   // (v000, v001)
        float2 g01 = gather_pair(p01, x0, x1, even);   // (v010, v011)
        float2 g10 = gather_pair(p10, x0, x1, even);   // (v100, v101)
        float2 g11 = gather_pair(p11, x0, x1, even);   // (v110, v111)

        float c00 = fmaf(wx, g00.y - g00.x, g00.x);
        float c01 = fmaf(wx, g01.y - g01.x, g01.x);
        float c10 = fmaf(wx, g10.y - g10.x, g10.x);
        float c11 = fmaf(wx, g11.y - g11.x, g11.x);
        float c0  = fmaf(wy, c01 - c00, c00);
        float c1  = fmaf(wy, c11 - c10, c10);
        res[k]    = fmaf(wz, c1 - c0, c0);
    }

    __stcs((float2*)(out + (size_t)b * SP + s), make_float2(res[0], res[1]));
}

extern "C" void kernel_launch(void* const* d_in, const int* in_sizes, int n_in,
                              void* d_out, int out_size)
{
    const float* img  = (const float*)d_in[0];
    const float* flow = (const float*)d_in[1];
    float* out = (float*)d_out;

    dim3 block(TX, TY, TZ);                             // 192 threads
    dim3 grid(WW / (TX * 2), HH / TY, (DD / TZ) * BB);  // 2 x 96 x 128
    warp3d_kernel<<<grid, block>>>(img, flow, out);
}

// round 17
// speedup vs baseline: 1.0914x; 1.0914x over previous
#include <cuda_runtime.h>

// Warper3d: 3D trilinear warp (grid_sample, align_corners=False, border pad).
//   img : [B=4, 1, D=64, H=192, W=192] f32
//   flow: [B=4, 3, D=64, H=192, W=192] f32
//   out : [B=4, 1, D=64, H=192, W=192] f32
//
// Model (R3-R15): L1tex-bound. R15's float2-pair gather achieved the lowest
// L1 work (51.5us-equiv) but exposed latency (L1 67%, dur 76.9). R11's
// 4-vox/thread structure is the most latency-tolerant. This version fuses
// them: 4 voxels/thread (x-pair x z-pair), float2-pair gathers (16 float2 +
// ~8 predicated scalars) all batched up-front, interpolation afterwards.
// (R16 bench was an infra failure — resubmitting unchanged.)

#define BB 4
#define DD 64
#define HH 192
#define WW 192
#define SP (DD * HH * WW)
#define HW (HH * WW)

#define BTX 96     // x-pair threads (covers all 192 x)
#define BTY 2      // y per block

// (v[x0], v[x1]) from one aligned float2 + rare predicated scalar.
// x0 in [0,191]; base = x0&~1 in [0,190] -> float2 is 8B aligned, in-bounds.
__device__ __forceinline__ float2 gather_pair(const float* __restrict__ row,
                                              int x0, int x1, bool even)
{
    float2 f = __ldg((const float2*)(row + (x0 & ~1)));
    float v0 = even ? f.x : f.y;
    float v1 = even ? f.y : __ldg(row + x1);   // predicated; x0==191 -> x1==191
    return make_float2(v0, v1);
}

__global__ __launch_bounds__(BTX * BTY)
void warp3d_kernel(const float* __restrict__ img,
                   const float* __restrict__ flow,
                   float* __restrict__ out)
{
    const int xp  = threadIdx.x * 2;                 // 0..190 even
    const int y   = blockIdx.x * BTY + threadIdx.y;  // grid.x = 96
    const int z0v = blockIdx.y * 2;                  // z pair base; grid.y = 32
    const int b   = blockIdx.z;

    const int s0 = (z0v * HH + y) * WW + xp;         // voxel pair at z0v
    const int s1 = s0 + HW;                          // voxel pair at z0v+1

    const float* fb = flow + (size_t)b * 3 * SP;
    // 6 independent coalesced flow loads issued up-front
    float2 fx0 = __ldcs((const float2*)(fb + s0));
    float2 fx1 = __ldcs((const float2*)(fb + s1));
    float2 fy0 = __ldcs((const float2*)(fb + SP + s0));
    float2 fy1 = __ldcs((const float2*)(fb + SP + s1));
    float2 fz0 = __ldcs((const float2*)(fb + 2 * SP + s0));
    float2 fz1 = __ldcs((const float2*)(fb + 2 * SP + s1));

    // Reference composition gx=2v/(S-1)-1; ix=((gx+1)*S-1)/2 == v*S/(S-1)-0.5
    const float KX = (float)WW / (float)(WW - 1);
    const float KY = (float)HH / (float)(HH - 1);
    const float KZ = (float)DD / (float)(DD - 1);

    const float* ib = img + (size_t)b * SP;

    const float fxa[4] = {fx0.x, fx0.y, fx1.x, fx1.y};
    const float fya[4] = {fy0.x, fy0.y, fy1.x, fy1.y};
    const float fza[4] = {fz0.x, fz0.y, fz1.x, fz1.y};

    // ---- phase 1: coordinates + all gathers batched
    float wxa[4], wya[4], wza[4];
    float2 g[4][4];                                   // [voxel][row] = (v_x0, v_x1)

    #pragma unroll
    for (int k = 0; k < 4; k++) {
        int xv = xp + (k & 1);
        int zv = z0v + (k >> 1);

        float ix = fmaf((float)xv + fxa[k], KX, -0.5f);
        float iy = fmaf((float)y  + fya[k], KY, -0.5f);
        float iz = fmaf((float)zv + fza[k], KZ, -0.5f);
        ix = fminf(fmaxf(ix, 0.0f), (float)(WW - 1));
        iy = fminf(fmaxf(iy, 0.0f), (float)(HH - 1));
        iz = fminf(fmaxf(iz, 0.0f), (float)(DD - 1));

        float x0f = floorf(ix); wxa[k] = ix - x0f;
        float y0f = floorf(iy); wya[k] = iy - y0f;
        float z0f = floorf(iz); wza[k] = iz - z0f;

        int x0 = (int)x0f; int x1 = min(x0 + 1, WW - 1);
        int y0 = (int)y0f; int y1 = min(y0 + 1, HH - 1);
        int z0 = (int)z0f; int z1 = min(z0 + 1, DD - 1);
        bool even = (x0 & 1) == 0;

        const float* p00 = ib + (z0 * HH + y0) * WW;
        const float* p01 = ib + (z0 * HH + y1) * WW;
        const float* p10 = ib + (z1 * HH + y0) * WW;
        const float* p11 = ib + (z1 * HH + y1) * WW;

        g[k][0] = gather_pair(p00, x0, x1, even);     // (v000, v001)
        g[k][1] = gather_pair(p01, x0, x1, even);     // (v010, v011)
        g[k][2] = gather_pair(p10, x0, x1, even);     // (v100, v101)
        g[k][3] = gather_pair(p11, x0, x1, even);     // (v110, v111)
    }

    // ---- phase 2: interpolation
    float r[4];
    #pragma unroll
    for (int k = 0; k < 4; k++) {
        float wx = wxa[k], wy = wya[k], wz = wza[k];
        float c00 = fmaf(wx, g[k][0].y - g[k][0].x, g[k][0].x);
        float c01 = fmaf(wx, g[k][1].y - g[k][1].x, g[k][1].x);
        float c10 = fmaf(wx, g[k][2].y - g[k][2].x, g[k][2].x);
        float c11 = fmaf(wx, g[k][3].y - g[k][3].x, g[k][3].x);
        float c0  = fmaf(wy, c01 - c00, c00);
        float c1  = fmaf(wy, c11 - c10, c10);
        r[k]      = fmaf(wz, c1 - c0, c0);
    }

    float* ob = out + (size_t)b * SP;
    __stcs((float2*)(ob + s0), make_float2(r[0], r[1]));
    __stcs((float2*)(ob + s1), make_float2(r[2], r[3]));
}

extern "C" void kernel_launch(void* const* d_in, const int* in_sizes, int n_in,
                              void* d_out, int out_size)
{
    const float* img  = (const float*)d_in[0];
    const float* flow = (const float*)d_in[1];
    float* out = (float*)d_out;

    dim3 block(BTX, BTY, 1);                 // 192 threads
    dim3 grid(HH / BTY, DD / 2, BB);         // 96 x 32 x 4
    warp3d_kernel<<<grid, block>>>(img, flow, out);
}